// round 6
// baseline (speedup 1.0000x reference)
#include <cuda_runtime.h>
#include <cuda_bf16.h>
#include <math.h>
#include <stdint.h>

#define NN 100000
#define NE 1000000
#define D  64
#define H  128
#define NL 4
#define NG 64
#define TILE_E 128
#define NT ((NE + TILE_E - 1) / TILE_E)   // 7813
#define EGRID 148
#define ETHREADS 512
#define GRID 4096
#define GSCALE 512.0f   // GRID / 8

typedef unsigned long long ull;

// ---------------- persistent device scratch ----------------
__device__ float g_h[NN * D];
__device__ float g_PQ[NN * 256];     // P (cols 0..127) | Q (cols 128..255)
__device__ float g_agg[NN * D];
__device__ float g_gidx[NE];         // dist * GSCALE
__device__ int   g_kind[NE];
__device__ float g_kt[NL * 2 * H];
__device__ float g_tab[NL * GRID * H];  // f_j(dist) table per layer
__device__ float g_sums[NG * D];
__device__ float g_cnt[NG];

// ---------------- f32x2 helpers ----------------
#define PACK2(d, x, y) asm("mov.b64 %0, {%1,%2};" : "=l"(d) : "r"(__float_as_uint(x)), "r"(__float_as_uint(y)))
#define UNPK2(lo, hi, v) asm("mov.b64 {%0,%1}, %2;" : "=r"(lo), "=r"(hi) : "l"(v))
#define FMA2(acc, a, b) asm("fma.rn.f32x2 %0, %1, %2, %0;" : "+l"(acc) : "l"(a), "l"(b))
#define ADD2(d, a, b)   asm("add.rn.f32x2 %0, %1, %2;" : "=l"(d) : "l"(a), "l"(b))
#define REDV4(p, v0, v1, v2, v3) \
    asm volatile("red.global.add.v4.f32 [%0], {%1,%2,%3,%4};" \
        :: "l"(p), "f"(v0), "f"(v1), "f"(v2), "f"(v3) : "memory")

// ---------------- init: node embed + zero everything ----------------
__global__ void k_init_h(const int* __restrict__ atoms, const float* __restrict__ embed) {
    int i = blockIdx.x * blockDim.x + threadIdx.x;
    if (i < NN * D) {
        g_h[i] = embed[atoms[i >> 6] * D + (i & 63)];
        g_agg[i] = 0.f;
    }
    if (i < NG * D) g_sums[i] = 0.f;
    if (i < NG) g_cnt[i] = 0.f;
}

// ---------------- edge prep (dist index + kind) + kind-table ----------------
__global__ void k_edge_prep(const int* __restrict__ ei, const float* __restrict__ coord,
                            const int* __restrict__ isr,
                            const float* __restrict__ subw, const float* __restrict__ W1,
                            const float* __restrict__ b1) {
    int e = blockIdx.x * blockDim.x + threadIdx.x;
    if (e < NE) {
        int s = ei[e], d = ei[NE + e];
        float dx = coord[s * 3 + 0] - coord[d * 3 + 0];
        float dy = coord[s * 3 + 1] - coord[d * 3 + 1];
        float dz = coord[s * 3 + 2] - coord[d * 3 + 2];
        float dist = sqrtf(dx * dx + dy * dy + dz * dz);
        g_gidx[e] = dist * GSCALE;
        g_kind[e] = (isr[s] != isr[d]) ? 1 : 0;
    } else {
        int t = e - NE;
        if (t < NL * 2 * H) {
            int l = t >> 8, kind = (t >> 7) & 1, j = t & 127;
            const float* W1l = W1 + (size_t)l * 160 * H;
            float v = b1[l * H + j];
#pragma unroll
            for (int g = 0; g < 16; g++)
                v += subw[kind * 16 + g] * W1l[(144 + g) * H + j];
            g_kt[t] = v;
        }
    }
}

// ---------------- rbf@W1c table build: thread per (l, grid-point) ----------------
__global__ void k_tab(const float* __restrict__ W1, int l0, int l1) {
    int t = blockIdx.x * blockDim.x + threadIdx.x;  // (l-l0)*GRID + i
    int nl = l1 - l0;
    if (t >= nl * GRID) return;
    int l = l0 + (t >> 12), i = t & (GRID - 1);
    float dd = (float)i * (1.0f / GSCALE);
    float r[16];
#pragma unroll
    for (int g = 0; g < 16; g++) {
        float u = dd - (float)g * (5.0f / 15.0f);
        r[g] = __expf(-4.5f * u * u);
    }
    const float* W1c = W1 + (size_t)l * 160 * H + 128 * H;
    float* outp = g_tab + ((size_t)l * GRID + i) * H;
    for (int j = 0; j < H; j++) {
        float v = 0.f;
#pragma unroll
        for (int g = 0; g < 16; g++) v += r[g] * W1c[g * H + j];
        outp[j] = v;
    }
}

// ---------------- node GEMM + fused relu(h+agg) ----------------
__global__ __launch_bounds__(256) void k_nodegemm(const float* __restrict__ W1, int l) {
    __shared__ float sW[64 * H];
    __shared__ float sh[64 * 18];
    const float* W1l = W1 + (size_t)l * 160 * H;
    int tid = threadIdx.x;
    int n0 = blockIdx.x * 16;
    for (int i = tid; i < 16 * 64; i += 256) {
        int k = i & 63, e = i >> 6;
        size_t idx = (size_t)(n0 + e) * D + k;
        float hv = g_h[idx];
        if (l > 0) {
            hv = fmaxf(hv + g_agg[idx], 0.f);
            g_h[idx] = hv;
            g_agg[idx] = 0.f;
        }
        sh[k * 18 + e] = hv;
    }
    int j = tid & 127;
    int ng = tid >> 7;
    for (int pass = 0; pass < 2; pass++) {
        __syncthreads();
        for (int i = tid; i < 64 * H; i += 256) sW[i] = W1l[pass * 64 * H + i];
        __syncthreads();
        ull acc[4];
#pragma unroll
        for (int q = 0; q < 4; q++) acc[q] = 0ull;
#pragma unroll 8
        for (int k = 0; k < 64; k++) {
            float w = sW[k * H + j];
            ull ww; PACK2(ww, w, w);
#pragma unroll
            for (int q = 0; q < 4; q++) {
                ull hv = *(const ull*)&sh[k * 18 + ng * 8 + q * 2];
                FMA2(acc[q], hv, ww);
            }
        }
#pragma unroll
        for (int q = 0; q < 4; q++) {
            uint32_t lo, hi; UNPK2(lo, hi, acc[q]);
            int nb = n0 + ng * 8 + q * 2;
            g_PQ[(size_t)nb * 256 + pass * 128 + j] = __uint_as_float(lo);
            g_PQ[(size_t)(nb + 1) * 256 + pass * 128 + j] = __uint_as_float(hi);
        }
    }
}

// ---------------- fused persistent edge kernel ----------------
// smem byte offsets (all 16B aligned)
#define M1_PITCH_B 1040                       // 130 ull per row
#define OFF_M1   0                            // 128 * 1040 = 133120
#define OFF_W2   133120                       // 32768
#define OFF_KT   165888                       // 1024
#define OFF_B2   166912                       // 256
#define OFF_META 167168                       // 2 * 128 * 16 = 4096
#define SMEM_EDGE 171264

__global__ __launch_bounds__(ETHREADS, 1) void k_edge(const float* __restrict__ W2,
                                                      const float* __restrict__ b2,
                                                      const int* __restrict__ ei, int l) {
    extern __shared__ char smem[];
    float* sW2  = (float*)(smem + OFF_W2);
    float* sKt  = (float*)(smem + OFF_KT);
    float* sB2  = (float*)(smem + OFF_B2);
    uint4* sMeta = (uint4*)(smem + OFF_META);

    int tid = threadIdx.x;
    const float* W2l = W2 + (size_t)l * H * D;
    const float* tabL = g_tab + (size_t)l * GRID * H;

    for (int i = tid; i < H * D; i += ETHREADS) sW2[i] = W2l[i];
    if (tid < 256) sKt[tid] = g_kt[l * 256 + tid];
    if (tid < 64) sB2[tid] = b2[l * D + tid];

    // phase A mapping: cols (jp, jp+64); 8 edge groups of 16
    const int jp = tid & 63;
    const int egA = tid >> 6;
    // phase B mapping: 8 d x 2 edges
    const int dq = tid & 7;
    const int egB = tid >> 3;

    const int chunk = (NT + EGRID - 1) / EGRID;   // 53
    int t0 = blockIdx.x * chunk;
    int t1 = t0 + chunk; if (t1 > NT) t1 = NT;

    // prefetch regs
    uint4 pfm = make_uint4(0u, (unsigned)-1, 0u, 0u);
    auto prefetch = [&](int tt) {
        if (tt >= NT || tid >= TILE_E) return;
        int e = tt * TILE_E + tid;
        if (e < NE) {
            pfm.x = (unsigned)ei[e];
            pfm.y = (unsigned)ei[NE + e];
            pfm.z = (unsigned)g_kind[e];
            pfm.w = __float_as_uint(g_gidx[e]);
        } else {
            pfm = make_uint4(0u, (unsigned)-1, 0u, 0u);
        }
    };
    auto store_pf = [&](int tt) {
        if (tt >= NT || tid >= TILE_E) return;
        sMeta[(tt & 1) * TILE_E + tid] = pfm;
    };

    prefetch(t0);
    store_pf(t0);
    __syncthreads();

    // hoisted kt values
    float kta0 = sKt[jp],      kta1 = sKt[128 + jp];
    float ktb0 = sKt[jp + 64], ktb1 = sKt[192 + jp];

    for (int t = t0; t < t1; t++) {
        int buf = t & 1;
        prefetch(t + 1);

        // ---- phase A ----
        {
            const uint4* ME = &sMeta[buf * TILE_E + egA * 16];
            char* rowA = smem + OFF_M1 + jp * M1_PITCH_B;
            char* rowB = smem + OFF_M1 + (jp + 64) * M1_PITCH_B;

            uint4 mA = ME[0], mB = ME[1];
            float gA[8], gB[8];
            auto issue = [&](const uint4& m, float* g) {
                int dn = (int)m.y;
                const float* Pp = g_PQ + (size_t)(dn < 0 ? 0 : dn) * 256;
                const float* Qp = g_PQ + (size_t)m.x * 256 + 128;
                float gx = __uint_as_float(m.w);
                int gi = (int)fminf(gx, (float)(GRID - 2));
                const float* T0 = tabL + (size_t)gi * H;
                g[0] = Pp[jp]; g[1] = Pp[jp + 64];
                g[2] = Qp[jp]; g[3] = Qp[jp + 64];
                g[4] = T0[jp]; g[5] = T0[jp + 64];
                g[6] = T0[H + jp]; g[7] = T0[H + 64 + jp];
            };
            auto computeS = [&](const uint4& m, const float* g, float& s0, float& s1) {
                float gx = __uint_as_float(m.w);
                int gi = (int)fminf(gx, (float)(GRID - 2));
                float fr = gx - (float)gi;
                float l0 = fmaf(fr, g[6] - g[4], g[4]);
                float l1 = fmaf(fr, g[7] - g[5], g[5]);
                float x0 = g[0] + g[2] + (m.z ? kta1 : kta0) + l0;
                float x1 = g[1] + g[3] + (m.z ? ktb1 : ktb0) + l1;
                s0 = __fdividef(x0, 1.f + __expf(-x0));
                s1 = __fdividef(x1, 1.f + __expf(-x1));
            };
            issue(mA, gA); issue(mB, gB);
#pragma unroll
            for (int pp = 0; pp < 8; pp++) {
                uint4 mC, mD; float gC[8], gD[8];
                if (pp < 7) {
                    mC = ME[2 * pp + 2]; mD = ME[2 * pp + 3];
                    issue(mC, gC); issue(mD, gD);
                }
                float sA0, sA1, sB0, sB1;
                computeS(mA, gA, sA0, sA1);
                computeS(mB, gB, sB0, sB1);
                ull dA0, dA1, dB0, dB1;
                PACK2(dA0, sA0, sA0); PACK2(dB0, sB0, sB0);
                PACK2(dA1, sA1, sA1); PACK2(dB1, sB1, sB1);
                ulonglong2 v0; v0.x = dA0; v0.y = dB0;
                ulonglong2 v1; v1.x = dA1; v1.y = dB1;
                *(ulonglong2*)(rowA + (egA * 16 + 2 * pp) * 8) = v0;
                *(ulonglong2*)(rowB + (egA * 16 + 2 * pp) * 8) = v1;
                mA = mC; mB = mD;
#pragma unroll
                for (int q = 0; q < 8; q++) { gA[q] = gC[q]; gB[q] = gD[q]; }
            }
        }
        store_pf(t + 1);
        __syncthreads();

        // ---- phase B: out = b2 + m1 @ W2; RED.v4 scatter ----
        {
            const char* mrow = smem + OFF_M1 + egB * 16;
            const float* w2p = sW2 + dq * 8;
            ull a0[4], a1[4];  // [d-pair][edge]
#pragma unroll
            for (int q = 0; q < 4; q++) { a0[q] = 0ull; a1[q] = 0ull; }
#pragma unroll 4
            for (int j = 0; j < H; j++) {
                ulonglong2 wv0 = *(const ulonglong2*)(w2p + j * 64);
                ulonglong2 wv1 = *(const ulonglong2*)(w2p + j * 64 + 4);
                ulonglong2 mm = *(const ulonglong2*)(mrow + j * M1_PITCH_B);
                FMA2(a0[0], mm.x, wv0.x); FMA2(a1[0], mm.y, wv0.x);
                FMA2(a0[1], mm.x, wv0.y); FMA2(a1[1], mm.y, wv0.y);
                FMA2(a0[2], mm.x, wv1.x); FMA2(a1[2], mm.y, wv1.x);
                FMA2(a0[3], mm.x, wv1.y); FMA2(a1[3], mm.y, wv1.y);
            }
            ulonglong2 bp0 = *(const ulonglong2*)(sB2 + dq * 8);
            ADD2(a0[0], a0[0], bp0.x); ADD2(a1[0], a1[0], bp0.x);
            ADD2(a0[1], a0[1], bp0.y); ADD2(a1[1], a1[1], bp0.y);
            ulonglong2 bp1 = *(const ulonglong2*)(sB2 + dq * 8 + 4);
            ADD2(a0[2], a0[2], bp1.x); ADD2(a1[2], a1[2], bp1.x);
            ADD2(a0[3], a0[3], bp1.y); ADD2(a1[3], a1[3], bp1.y);

            int dn0 = (int)sMeta[buf * TILE_E + 2 * egB].y;
            int dn1 = (int)sMeta[buf * TILE_E + 2 * egB + 1].y;
            uint32_t u0, u1, u2, u3, u4, u5, u6, u7;
            if (dn0 >= 0) {
                float* p = &g_agg[(size_t)dn0 * D + dq * 8];
                UNPK2(u0, u1, a0[0]); UNPK2(u2, u3, a0[1]);
                UNPK2(u4, u5, a0[2]); UNPK2(u6, u7, a0[3]);
                REDV4(p, __uint_as_float(u0), __uint_as_float(u1), __uint_as_float(u2), __uint_as_float(u3));
                REDV4(p + 4, __uint_as_float(u4), __uint_as_float(u5), __uint_as_float(u6), __uint_as_float(u7));
            }
            if (dn1 >= 0) {
                float* p = &g_agg[(size_t)dn1 * D + dq * 8];
                UNPK2(u0, u1, a1[0]); UNPK2(u2, u3, a1[1]);
                UNPK2(u4, u5, a1[2]); UNPK2(u6, u7, a1[3]);
                REDV4(p, __uint_as_float(u0), __uint_as_float(u1), __uint_as_float(u2), __uint_as_float(u3));
                REDV4(p + 4, __uint_as_float(u4), __uint_as_float(u5), __uint_as_float(u6), __uint_as_float(u7));
            }
        }
        __syncthreads();
    }
}

// ---------------- pooling (relu fused) ----------------
__global__ void k_pool(const int* __restrict__ batch) {
    int i = blockIdx.x * blockDim.x + threadIdx.x;
    if (i >= NN * D) return;
    int n = i >> 6, d = i & 63;
    float v = fmaxf(g_h[i] + g_agg[i], 0.f);
    atomicAdd(&g_sums[batch[n] * D + d], v);
}

__global__ void k_count(const int* __restrict__ batch) {
    int n = blockIdx.x * blockDim.x + threadIdx.x;
    if (n >= NN) return;
    int b = batch[n];
    unsigned mask = __activemask();
    unsigned m = __match_any_sync(mask, b);
    int leader = __ffs(m) - 1;
    if ((threadIdx.x & 31) == leader) atomicAdd(&g_cnt[b], (float)__popc(m));
}

__global__ void k_final(const float* __restrict__ fcw, const float* __restrict__ fcb,
                        float* __restrict__ out) {
    int g = threadIdx.x;
    if (g < NG) {
        float c = fmaxf(g_cnt[g], 1.f);
        float s = 0.f;
#pragma unroll
        for (int d = 0; d < D; d++) s += g_sums[g * D + d] * fcw[d];
        out[g] = s / c + fcb[0];
    }
}

extern "C" void kernel_launch(void* const* d_in, const int* in_sizes, int n_in,
                              void* d_out, int out_size) {
    const int*   atoms = (const int*)d_in[0];
    const int*   ei    = (const int*)d_in[1];
    const float* coord = (const float*)d_in[2];
    const int*   isr   = (const int*)d_in[3];
    const int*   batch = (const int*)d_in[4];
    const float* embed = (const float*)d_in[5];
    const float* subw  = (const float*)d_in[6];
    const float* W1    = (const float*)d_in[7];
    const float* b1    = (const float*)d_in[8];
    const float* W2    = (const float*)d_in[9];
    const float* b2    = (const float*)d_in[10];
    const float* fcw   = (const float*)d_in[11];
    const float* fcb   = (const float*)d_in[12];
    float* out = (float*)d_out;

    cudaFuncSetAttribute(k_edge, cudaFuncAttributeMaxDynamicSharedMemorySize, SMEM_EDGE);

    const int T = 256;
    k_init_h<<<(NN * D + T - 1) / T, T>>>(atoms, embed);                       // 0
    k_edge_prep<<<(NE + 1024 + T - 1) / T, T>>>(ei, coord, isr, subw, W1, b1); // 1
    k_tab<<<(2 * GRID + T - 1) / T, T>>>(W1, 0, 2);                            // 2
    k_tab<<<(2 * GRID + T - 1) / T, T>>>(W1, 2, 4);                            // 3

    for (int l = 0; l < NL; l++) {
        k_nodegemm<<<NN / 16, 256>>>(W1, l);                                   // 4,6,8,10
        k_edge<<<EGRID, ETHREADS, SMEM_EDGE>>>(W2, b2, ei, l);                 // 5,7,9,11
    }

    k_pool<<<(NN * D + T - 1) / T, T>>>(batch);
    k_count<<<(NN + T - 1) / T, T>>>(batch);
    k_final<<<1, 64>>>(fcw, fcb, out);
}

// round 8
// speedup vs baseline: 1.0100x; 1.0100x over previous
#include <cuda_runtime.h>
#include <cuda_bf16.h>
#include <math.h>
#include <stdint.h>

#define NN 100000
#define NE 1000000
#define D  64
#define H  128
#define NL 4
#define NG 64
#define TILE_E 64
#define NT ((NE + TILE_E - 1) / TILE_E)   // 15625
#define EGRID 296
#define ETHREADS 256

typedef unsigned long long ull;

// ---------------- persistent device scratch ----------------
__device__ float g_h[NN * D];
__device__ float g_PQ[NN * 256];     // P (cols 0..127) | Q (cols 128..255)
__device__ float g_agg[NN * D];
__device__ float g_rbf[(size_t)NE * 16];
__device__ int   g_kind[NE];
__device__ float g_kt[NL * 2 * H];
__device__ float g_sums[NG * D];
__device__ float g_cnt[NG];

// ---------------- f32x2 helpers ----------------
#define PACK2(d, x, y) asm("mov.b64 %0, {%1,%2};" : "=l"(d) : "r"(__float_as_uint(x)), "r"(__float_as_uint(y)))
#define UNPK2(lo, hi, v) asm("mov.b64 {%0,%1}, %2;" : "=r"(lo), "=r"(hi) : "l"(v))
#define FMA2(acc, a, b) asm("fma.rn.f32x2 %0, %1, %2, %0;" : "+l"(acc) : "l"(a), "l"(b))
#define ADD2(d, a, b)   asm("add.rn.f32x2 %0, %1, %2;" : "=l"(d) : "l"(a), "l"(b))
#define REDV4(p, v0, v1, v2, v3) \
    asm volatile("red.global.add.v4.f32 [%0], {%1,%2,%3,%4};" \
        :: "l"(p), "f"(v0), "f"(v1), "f"(v2), "f"(v3) : "memory")

// ---------------- init: node embed + zero everything ----------------
__global__ void k_init_h(const int* __restrict__ atoms, const float* __restrict__ embed) {
    int i = blockIdx.x * blockDim.x + threadIdx.x;
    if (i < NN * D) {
        g_h[i] = embed[atoms[i >> 6] * D + (i & 63)];
        g_agg[i] = 0.f;
    }
    if (i < NG * D) g_sums[i] = 0.f;
    if (i < NG) g_cnt[i] = 0.f;
}

// ---------------- edge prep (rbf + kind) + kind-table ----------------
__global__ void k_edge_prep(const int* __restrict__ ei, const float* __restrict__ coord,
                            const int* __restrict__ isr,
                            const float* __restrict__ subw, const float* __restrict__ W1,
                            const float* __restrict__ b1) {
    int e = blockIdx.x * blockDim.x + threadIdx.x;
    if (e < NE) {
        int s = ei[e], d = ei[NE + e];
        float dx = coord[s * 3 + 0] - coord[d * 3 + 0];
        float dy = coord[s * 3 + 1] - coord[d * 3 + 1];
        float dz = coord[s * 3 + 2] - coord[d * 3 + 2];
        float dist = sqrtf(dx * dx + dy * dy + dz * dz);
        const float coeff = -4.5f;
        float o[16];
#pragma unroll
        for (int g = 0; g < 16; g++) {
            float t = dist - (float)g * (5.0f / 15.0f);
            o[g] = __expf(coeff * t * t);
        }
        float4* dp = (float4*)&g_rbf[(size_t)e * 16];
        dp[0] = make_float4(o[0], o[1], o[2], o[3]);
        dp[1] = make_float4(o[4], o[5], o[6], o[7]);
        dp[2] = make_float4(o[8], o[9], o[10], o[11]);
        dp[3] = make_float4(o[12], o[13], o[14], o[15]);
        g_kind[e] = (isr[s] != isr[d]) ? 1 : 0;
    } else {
        int t = e - NE;
        if (t < NL * 2 * H) {
            int l = t >> 8, kind = (t >> 7) & 1, j = t & 127;
            const float* W1l = W1 + (size_t)l * 160 * H;
            float v = b1[l * H + j];
#pragma unroll
            for (int g = 0; g < 16; g++)
                v += subw[kind * 16 + g] * W1l[(144 + g) * H + j];
            g_kt[t] = v;
        }
    }
}

// ---------------- node GEMM + fused relu(h+agg) (R3 shape) ----------------
__global__ __launch_bounds__(256) void k_nodegemm(const float* __restrict__ W1, int l) {
    __shared__ float sW[64 * H];
    __shared__ float sh[64 * 18];
    const float* W1l = W1 + (size_t)l * 160 * H;
    int tid = threadIdx.x;
    int n0 = blockIdx.x * 16;
    for (int i = tid; i < 16 * 64; i += 256) {
        int k = i & 63, e = i >> 6;
        size_t idx = (size_t)(n0 + e) * D + k;
        float hv = g_h[idx];
        if (l > 0) {
            hv = fmaxf(hv + g_agg[idx], 0.f);
            g_h[idx] = hv;
            g_agg[idx] = 0.f;
        }
        sh[k * 18 + e] = hv;
    }
    int j = tid & 127;
    int ng = tid >> 7;
    for (int pass = 0; pass < 2; pass++) {
        __syncthreads();
        for (int i = tid; i < 64 * H; i += 256) sW[i] = W1l[pass * 64 * H + i];
        __syncthreads();
        ull acc[4];
#pragma unroll
        for (int q = 0; q < 4; q++) acc[q] = 0ull;
#pragma unroll 8
        for (int k = 0; k < 64; k++) {
            float w = sW[k * H + j];
            ull ww; PACK2(ww, w, w);
#pragma unroll
            for (int q = 0; q < 4; q++) {
                ull hv = *(const ull*)&sh[k * 18 + ng * 8 + q * 2];
                FMA2(acc[q], hv, ww);
            }
        }
#pragma unroll
        for (int q = 0; q < 4; q++) {
            uint32_t lo, hi; UNPK2(lo, hi, acc[q]);
            int nb = n0 + ng * 8 + q * 2;
            g_PQ[(size_t)nb * 256 + pass * 128 + j] = __uint_as_float(lo);
            g_PQ[(size_t)(nb + 1) * 256 + pass * 128 + j] = __uint_as_float(hi);
        }
    }
}

// ---------------- fused persistent edge kernel (2 CTA/SM) ----------------
// smem byte offsets (16B aligned)
#define M1U_PITCH 66                          // ull per j-row (64 e + 2 pad)
#define OFF_M1   0                            // 128 * 66 * 8 = 67584
#define OFF_W2   67584                        // 128*64*4 = 32768
#define OFF_RBF  100352                       // 64*16 ull = 8192
#define OFF_B2   108544                       // 256
#define OFF_DST  108800                       // 256
#define OFF_SRC  109056                       // 256
#define OFF_KND  109312                       // 256
#define SMEM_EDGE 109568

__global__ __launch_bounds__(ETHREADS, 2) void k_edge(const float* __restrict__ W1,
                                                      const float* __restrict__ W2,
                                                      const float* __restrict__ b2,
                                                      const int* __restrict__ ei, int l) {
    extern __shared__ char smem[];
    ull*   sM1u = (ull*)(smem + OFF_M1);
    float* sW2  = (float*)(smem + OFF_W2);
    ull*   sRbf = (ull*)(smem + OFF_RBF);
    float* sB2  = (float*)(smem + OFF_B2);
    int*   sDst = (int*)(smem + OFF_DST);
    int*   sSrc = (int*)(smem + OFF_SRC);
    int*   sKnd = (int*)(smem + OFF_KND);

    int tid = threadIdx.x;
    const float* W1l = W1 + (size_t)l * 160 * H;
    const float* W2l = W2 + (size_t)l * H * D;

    for (int i = tid; i < H * D; i += ETHREADS) sW2[i] = W2l[i];
    if (tid < 64) sB2[tid] = b2[l * D + tid];

    // phase A mapping: cols (jp, jp+64); 4 edge groups of 16
    const int jp = tid & 63;
    const int egA = tid >> 6;
    // phase B mapping: 16 d-quads x 16 edge groups of 4
    const int dq = tid & 15;
    const int egB = tid >> 4;
    const int dbase = dq * 4;
    const int ebase = egB * 4;

    // hoisted per-layer constants from GLOBAL (once per CTA)
    ull w1c2[16];
#pragma unroll
    for (int g = 0; g < 16; g++) {
        const float* W1c = W1l + (128 + g) * H;
        PACK2(w1c2[g], W1c[jp], W1c[jp + 64]);
    }
    ull ktv0, ktv1;
    {
        const float* ktp = g_kt + l * 256;
        PACK2(ktv0, ktp[jp], ktp[jp + 64]);
        PACK2(ktv1, ktp[128 + jp], ktp[192 + jp]);
    }

    const int chunk = (NT + EGRID - 1) / EGRID;   // 53
    int t0 = blockIdx.x * chunk;
    int t1 = t0 + chunk; if (t1 > NT) t1 = NT;

    for (int t = t0; t < t1; t++) {
        int e0 = t * TILE_E;
        // ---- tile metadata + rbf (dup) ----
        if (tid < TILE_E) {
            int e = e0 + tid;
            bool v = e < NE;
            sSrc[tid] = v ? ei[e] : 0;
            sDst[tid] = v ? ei[NE + e] : -1;
            sKnd[tid] = v ? g_kind[e] : 0;
        }
        {
            // 64 edges * 4 float4 = 256 float4; one per thread
            int e = e0 + (tid >> 2);
            float4 r = (e < NE) ? ((const float4*)g_rbf)[(size_t)t * 256 + tid]
                                : make_float4(0.f, 0.f, 0.f, 0.f);
            ull* rp = &sRbf[(size_t)tid * 4];
            PACK2(rp[0], r.x, r.x);
            PACK2(rp[1], r.y, r.y);
            PACK2(rp[2], r.z, r.z);
            PACK2(rp[3], r.w, r.w);
        }
        __syncthreads();

        // ---- phase A: m1 = silu(P[dst]+Q[src]+kt[kind]+rbf@W1c), dup j-major ----
        {
            const int eb = egA * 16;
            // one-ahead pipeline for P/Q gathers
            int dn0 = sDst[eb], sn0 = sSrc[eb];
            const float* Pp = g_PQ + (size_t)(dn0 < 0 ? 0 : dn0) * 256;
            const float* Qp = g_PQ + (size_t)sn0 * 256 + 128;
            float p0 = Pp[jp], p1 = Pp[jp + 64];
            float q0 = Qp[jp], q1 = Qp[jp + 64];
#pragma unroll
            for (int ee = 0; ee < 16; ee++) {
                int e = eb + ee;
                float np0 = 0.f, np1 = 0.f, nq0 = 0.f, nq1 = 0.f;
                if (ee < 15) {
                    int dnn = sDst[e + 1], snn = sSrc[e + 1];
                    const float* Pn = g_PQ + (size_t)(dnn < 0 ? 0 : dnn) * 256;
                    const float* Qn = g_PQ + (size_t)snn * 256 + 128;
                    np0 = Pn[jp]; np1 = Pn[jp + 64];
                    nq0 = Qn[jp]; nq1 = Qn[jp + 64];
                }
                ull acc;
                PACK2(acc, p0 + q0, p1 + q1);
                ADD2(acc, acc, sKnd[e] ? ktv1 : ktv0);
                const ulonglong2* rb2 = (const ulonglong2*)&sRbf[(size_t)e * 16];
#pragma unroll
                for (int g = 0; g < 8; g++) {
                    ulonglong2 rv = rb2[g];
                    FMA2(acc, rv.x, w1c2[2 * g]);
                    FMA2(acc, rv.y, w1c2[2 * g + 1]);
                }
                uint32_t u0, u1; UNPK2(u0, u1, acc);
                float x0 = __uint_as_float(u0), x1 = __uint_as_float(u1);
                float s0 = __fdividef(x0, 1.f + __expf(-x0));
                float s1 = __fdividef(x1, 1.f + __expf(-x1));
                ull d0, d1;
                PACK2(d0, s0, s0);
                PACK2(d1, s1, s1);
                sM1u[(size_t)jp * M1U_PITCH + e] = d0;
                sM1u[(size_t)(jp + 64) * M1U_PITCH + e] = d1;
                p0 = np0; p1 = np1; q0 = nq0; q1 = nq1;
            }
        }
        __syncthreads();

        // ---- phase B: out = b2 + m1 @ W2; RED.v4 scatter ----
        {
            ull a[8];  // [e(4)][d-pair(2)]
#pragma unroll
            for (int q = 0; q < 8; q++) a[q] = 0ull;
#pragma unroll 4
            for (int j = 0; j < H; j++) {
                ulonglong2 wv  = *(const ulonglong2*)&sW2[j * 64 + dbase];
                ulonglong2 m01 = *(const ulonglong2*)&sM1u[(size_t)j * M1U_PITCH + ebase];
                ulonglong2 m23 = *(const ulonglong2*)&sM1u[(size_t)j * M1U_PITCH + ebase + 2];
                FMA2(a[0], m01.x, wv.x); FMA2(a[1], m01.x, wv.y);
                FMA2(a[2], m01.y, wv.x); FMA2(a[3], m01.y, wv.y);
                FMA2(a[4], m23.x, wv.x); FMA2(a[5], m23.x, wv.y);
                FMA2(a[6], m23.y, wv.x); FMA2(a[7], m23.y, wv.y);
            }
            ulonglong2 bp = *(const ulonglong2*)&sB2[dbase];
#pragma unroll
            for (int k = 0; k < 4; k++) {
                ADD2(a[2 * k], a[2 * k], bp.x);
                ADD2(a[2 * k + 1], a[2 * k + 1], bp.y);
            }
            uint32_t u0, u1, u2, u3;
#pragma unroll
            for (int k = 0; k < 4; k++) {
                int dn = sDst[ebase + k];
                if (dn >= 0) {
                    UNPK2(u0, u1, a[2 * k]);
                    UNPK2(u2, u3, a[2 * k + 1]);
                    REDV4(&g_agg[(size_t)dn * D + dbase],
                          __uint_as_float(u0), __uint_as_float(u1),
                          __uint_as_float(u2), __uint_as_float(u3));
                }
            }
        }
        __syncthreads();
    }
}

// ---------------- pooling (relu fused) ----------------
__global__ void k_pool(const int* __restrict__ batch) {
    int i = blockIdx.x * blockDim.x + threadIdx.x;
    if (i >= NN * D) return;
    int n = i >> 6, d = i & 63;
    float v = fmaxf(g_h[i] + g_agg[i], 0.f);
    atomicAdd(&g_sums[batch[n] * D + d], v);
}

__global__ void k_count(const int* __restrict__ batch) {
    int n = blockIdx.x * blockDim.x + threadIdx.x;
    if (n >= NN) return;
    int b = batch[n];
    unsigned mask = __activemask();
    unsigned m = __match_any_sync(mask, b);
    int leader = __ffs(m) - 1;
    if ((threadIdx.x & 31) == leader) atomicAdd(&g_cnt[b], (float)__popc(m));
}

__global__ void k_final(const float* __restrict__ fcw, const float* __restrict__ fcb,
                        float* __restrict__ out) {
    int g = threadIdx.x;
    if (g < NG) {
        float c = fmaxf(g_cnt[g], 1.f);
        float s = 0.f;
#pragma unroll
        for (int d = 0; d < D; d++) s += g_sums[g * D + d] * fcw[d];
        out[g] = s / c + fcb[0];
    }
}

extern "C" void kernel_launch(void* const* d_in, const int* in_sizes, int n_in,
                              void* d_out, int out_size) {
    const int*   atoms = (const int*)d_in[0];
    const int*   ei    = (const int*)d_in[1];
    const float* coord = (const float*)d_in[2];
    const int*   isr   = (const int*)d_in[3];
    const int*   batch = (const int*)d_in[4];
    const float* embed = (const float*)d_in[5];
    const float* subw  = (const float*)d_in[6];
    const float* W1    = (const float*)d_in[7];
    const float* b1    = (const float*)d_in[8];
    const float* W2    = (const float*)d_in[9];
    const float* b2    = (const float*)d_in[10];
    const float* fcw   = (const float*)d_in[11];
    const float* fcb   = (const float*)d_in[12];
    float* out = (float*)d_out;

    cudaFuncSetAttribute(k_edge, cudaFuncAttributeMaxDynamicSharedMemorySize, SMEM_EDGE);

    const int T = 256;
    k_init_h<<<(NN * D + T - 1) / T, T>>>(atoms, embed);                       // 0
    k_edge_prep<<<(NE + 1024 + T - 1) / T, T>>>(ei, coord, isr, subw, W1, b1); // 1

    for (int l = 0; l < NL; l++) {
        k_nodegemm<<<NN / 16, 256>>>(W1, l);                                   // 2,4,6,8
        k_edge<<<EGRID, ETHREADS, SMEM_EDGE>>>(W1, W2, b2, ei, l);             // 3,5,7,9
    }

    k_pool<<<(NN * D + T - 1) / T, T>>>(batch);
    k_count<<<(NN + T - 1) / T, T>>>(batch);
    k_final<<<1, 64>>>(fcw, fcb, out);
}

// round 11
// speedup vs baseline: 1.4310x; 1.4168x over previous
#include <cuda_runtime.h>
#include <cuda_bf16.h>
#include <math.h>
#include <stdint.h>

#define NN 100000
#define NE 1000000
#define D  64
#define H  128
#define NL 4
#define NG 64
#define TILE_E 128
#define NT ((NE + TILE_E - 1) / TILE_E)   // 7813
#define EGRID 148
#define ETHREADS 512
#define M1P 132    // float pitch of m1 rows (16B-aligned rows, j-major)

typedef unsigned long long ull;

// ---------------- persistent device scratch ----------------
__device__ float g_h[NN * D];
__device__ float g_PQ[NN * 256];     // P (cols 0..127) | Q (cols 128..255)
__device__ float g_agg[NN * D];
__device__ float g_rbf[(size_t)NE * 16];
__device__ int   g_kind[NE];
__device__ float g_kt[NL * 2 * H];
__device__ float g_sums[NG * D];
__device__ float g_cnt[NG];

// ---------------- f32x2 helpers ----------------
#define PACK2(d, x, y) asm("mov.b64 %0, {%1,%2};" : "=l"(d) : "r"(__float_as_uint(x)), "r"(__float_as_uint(y)))
#define UNPK2(lo, hi, v) asm("mov.b64 {%0,%1}, %2;" : "=r"(lo), "=r"(hi) : "l"(v))
#define FMA2(acc, a, b) asm("fma.rn.f32x2 %0, %1, %2, %0;" : "+l"(acc) : "l"(a), "l"(b))
#define ADD2(d, a, b)   asm("add.rn.f32x2 %0, %1, %2;" : "=l"(d) : "l"(a), "l"(b))
#define REDV2(p, v0, v1) \
    asm volatile("red.global.add.v2.f32 [%0], {%1,%2};" \
        :: "l"(p), "f"(v0), "f"(v1) : "memory")

// ---------------- init: node embed + zero everything ----------------
__global__ void k_init_h(const int* __restrict__ atoms, const float* __restrict__ embed) {
    int i = blockIdx.x * blockDim.x + threadIdx.x;
    if (i < NN * D) {
        g_h[i] = embed[atoms[i >> 6] * D + (i & 63)];
        g_agg[i] = 0.f;
    }
    if (i < NG * D) g_sums[i] = 0.f;
    if (i < NG) g_cnt[i] = 0.f;
}

// ---------------- edge prep (rbf + kind) + kind-table ----------------
__global__ void k_edge_prep(const int* __restrict__ ei, const float* __restrict__ coord,
                            const int* __restrict__ isr,
                            const float* __restrict__ subw, const float* __restrict__ W1,
                            const float* __restrict__ b1) {
    int e = blockIdx.x * blockDim.x + threadIdx.x;
    if (e < NE) {
        int s = ei[e], d = ei[NE + e];
        float dx = coord[s * 3 + 0] - coord[d * 3 + 0];
        float dy = coord[s * 3 + 1] - coord[d * 3 + 1];
        float dz = coord[s * 3 + 2] - coord[d * 3 + 2];
        float dist = sqrtf(dx * dx + dy * dy + dz * dz);
        const float coeff = -4.5f;
        float o[16];
#pragma unroll
        for (int g = 0; g < 16; g++) {
            float t = dist - (float)g * (5.0f / 15.0f);
            o[g] = __expf(coeff * t * t);
        }
        float4* dp = (float4*)&g_rbf[(size_t)e * 16];
        dp[0] = make_float4(o[0], o[1], o[2], o[3]);
        dp[1] = make_float4(o[4], o[5], o[6], o[7]);
        dp[2] = make_float4(o[8], o[9], o[10], o[11]);
        dp[3] = make_float4(o[12], o[13], o[14], o[15]);
        g_kind[e] = (isr[s] != isr[d]) ? 1 : 0;
    } else {
        int t = e - NE;
        if (t < NL * 2 * H) {
            int l = t >> 8, kind = (t >> 7) & 1, j = t & 127;
            const float* W1l = W1 + (size_t)l * 160 * H;
            float v = b1[l * H + j];
#pragma unroll
            for (int g = 0; g < 16; g++)
                v += subw[kind * 16 + g] * W1l[(144 + g) * H + j];
            g_kt[t] = v;
        }
    }
}

// ---------------- node GEMM + fused relu(h+agg) (R3 shape) ----------------
__global__ __launch_bounds__(256) void k_nodegemm(const float* __restrict__ W1, int l) {
    __shared__ float sW[64 * H];
    __shared__ float sh[64 * 18];
    const float* W1l = W1 + (size_t)l * 160 * H;
    int tid = threadIdx.x;
    int n0 = blockIdx.x * 16;
    for (int i = tid; i < 16 * 64; i += 256) {
        int k = i & 63, e = i >> 6;
        size_t idx = (size_t)(n0 + e) * D + k;
        float hv = g_h[idx];
        if (l > 0) {
            hv = fmaxf(hv + g_agg[idx], 0.f);
            g_h[idx] = hv;
            g_agg[idx] = 0.f;
        }
        sh[k * 18 + e] = hv;
    }
    int j = tid & 127;
    int ng = tid >> 7;
    for (int pass = 0; pass < 2; pass++) {
        __syncthreads();
        for (int i = tid; i < 64 * H; i += 256) sW[i] = W1l[pass * 64 * H + i];
        __syncthreads();
        ull acc[4];
#pragma unroll
        for (int q = 0; q < 4; q++) acc[q] = 0ull;
#pragma unroll 8
        for (int k = 0; k < 64; k++) {
            float w = sW[k * H + j];
            ull ww; PACK2(ww, w, w);
#pragma unroll
            for (int q = 0; q < 4; q++) {
                ull hv = *(const ull*)&sh[k * 18 + ng * 8 + q * 2];
                FMA2(acc[q], hv, ww);
            }
        }
#pragma unroll
        for (int q = 0; q < 4; q++) {
            uint32_t lo, hi; UNPK2(lo, hi, acc[q]);
            int nb = n0 + ng * 8 + q * 2;
            g_PQ[(size_t)nb * 256 + pass * 128 + j] = __uint_as_float(lo);
            g_PQ[(size_t)(nb + 1) * 256 + pass * 128 + j] = __uint_as_float(hi);
        }
    }
}

// ---------------- fused persistent edge kernel ----------------
// smem byte offsets
#define OFF_M1   0         // float[128][132] = 67584
#define OFF_W2   67584     // float[128*64] = 32768
#define OFF_RBF  100352    // ull[128*16] = 16384 (duplicated pairs; reads are broadcast)
#define OFF_DST  116736    // 512
#define OFF_SRC  117248    // 512
#define OFF_KND  117760    // 512
#define SMEM_EDGE 118272

__global__ __launch_bounds__(ETHREADS, 1) void k_edge(const float* __restrict__ W1,
                                                      const float* __restrict__ W2,
                                                      const float* __restrict__ b2,
                                                      const int* __restrict__ ei, int l) {
    extern __shared__ char smem[];
    float* sM1  = (float*)(smem + OFF_M1);
    float* sW2  = (float*)(smem + OFF_W2);
    ull*   sRbf = (ull*)(smem + OFF_RBF);
    int*   sDst = (int*)(smem + OFF_DST);
    int*   sSrc = (int*)(smem + OFF_SRC);
    int*   sKnd = (int*)(smem + OFF_KND);

    int tid = threadIdx.x;
    const float* W1l = W1 + (size_t)l * 160 * H;
    const float* W2l = W2 + (size_t)l * H * D;

    for (int i = tid; i < H * D; i += ETHREADS) sW2[i] = W2l[i];
    __syncthreads();

    // phase A mapping: cols (jp, jp+64); 8 edge groups of 16
    const int jp = tid & 63;
    const int egA = tid >> 6;
    // phase B mapping: 32 d-pairs x 16 edge groups of 8
    const int dp = tid & 31;
    const int egB = tid >> 5;
    const int dd = dp * 2;
    const int ebase = egB * 8;

    // hoisted per-layer constants
    ull w1c2[16];
#pragma unroll
    for (int g = 0; g < 16; g++) {
        const float* W1c = W1l + (128 + g) * H;
        PACK2(w1c2[g], W1c[jp], W1c[jp + 64]);
    }
    ull ktv0, ktv1;
    {
        const float* ktp = g_kt + l * 256;
        PACK2(ktv0, ktp[jp], ktp[jp + 64]);
        PACK2(ktv1, ktp[128 + jp], ktp[192 + jp]);
    }
    ull bp0, bp1;
    {
        float b0 = b2[l * D + dd], b1v = b2[l * D + dd + 1];
        PACK2(bp0, b0, b0);
        PACK2(bp1, b1v, b1v);
    }

    const int chunk = (NT + EGRID - 1) / EGRID;   // 53
    int t0 = blockIdx.x * chunk;
    int t1 = t0 + chunk; if (t1 > NT) t1 = NT;
    if (t0 >= t1) return;

    for (int t = t0; t < t1; t++) {
        int e0 = t * TILE_E;
        // ---- tile metadata + duplicated rbf ----
        if (tid < TILE_E) {
            int e = e0 + tid;
            bool v = e < NE;
            sSrc[tid] = v ? ei[e] : 0;
            sDst[tid] = v ? ei[NE + e] : -1;
            sKnd[tid] = v ? g_kind[e] : 0;
        }
        {
            // 128 edges * 4 float4 = 512 float4; one per thread, duplicated store
            int e = e0 + (tid >> 2);
            float4 r = (e < NE) ? ((const float4*)g_rbf)[(size_t)t * 512 + tid]
                                : make_float4(0.f, 0.f, 0.f, 0.f);
            ull* rp = &sRbf[(size_t)tid * 4];
            PACK2(rp[0], r.x, r.x);
            PACK2(rp[1], r.y, r.y);
            PACK2(rp[2], r.z, r.z);
            PACK2(rp[3], r.w, r.w);
        }
        __syncthreads();

        // ---- phase A: m1 = silu(P[dst]+Q[src]+kt[kind]+rbf@W1c) ----
        {
            const int eb = egA * 16;
#pragma unroll 4
            for (int ee = 0; ee < 16; ee++) {
                int e = eb + ee;
                int dn = sDst[e], sn = sSrc[e];
                const float* Pp = g_PQ + (size_t)(dn < 0 ? 0 : dn) * 256;
                const float* Qp = g_PQ + (size_t)sn * 256 + 128;
                float p0 = Pp[jp], p1 = Pp[jp + 64];
                float q0 = Qp[jp], q1 = Qp[jp + 64];
                ull acc;
                PACK2(acc, p0 + q0, p1 + q1);
                ADD2(acc, acc, sKnd[e] ? ktv1 : ktv0);
                const ulonglong2* rb = (const ulonglong2*)&sRbf[(size_t)e * 16];
#pragma unroll
                for (int g = 0; g < 8; g++) {
                    ulonglong2 rv = rb[g];
                    FMA2(acc, rv.x, w1c2[2 * g]);
                    FMA2(acc, rv.y, w1c2[2 * g + 1]);
                }
                uint32_t u0, u1; UNPK2(u0, u1, acc);
                float x0 = __uint_as_float(u0), x1 = __uint_as_float(u1);
                sM1[jp * M1P + e]        = __fdividef(x0, 1.f + __expf(-x0));
                sM1[(jp + 64) * M1P + e] = __fdividef(x1, 1.f + __expf(-x1));
            }
        }
        __syncthreads();

        // ---- phase B: out = b2 + m1 @ W2 (2d x 8e, native e-pair FMA2); RED.v2 scatter ----
        {
            ull acc[8];  // [e-pair(4)][d(2)]
#pragma unroll
            for (int q = 0; q < 8; q++) acc[q] = 0ull;
#pragma unroll 4
            for (int j = 0; j < H; j++) {
                ulonglong2 mA = *(const ulonglong2*)&sM1[j * M1P + ebase];      // e0..e3
                ulonglong2 mB = *(const ulonglong2*)&sM1[j * M1P + ebase + 4];  // e4..e7
                float2 wf = *(const float2*)&sW2[j * 64 + dd];
                ull w0, w1;
                PACK2(w0, wf.x, wf.x);
                PACK2(w1, wf.y, wf.y);
                FMA2(acc[0], mA.x, w0); FMA2(acc[1], mA.x, w1);
                FMA2(acc[2], mA.y, w0); FMA2(acc[3], mA.y, w1);
                FMA2(acc[4], mB.x, w0); FMA2(acc[5], mB.x, w1);
                FMA2(acc[6], mB.y, w0); FMA2(acc[7], mB.y, w1);
            }
#pragma unroll
            for (int ep = 0; ep < 4; ep++) {
                ADD2(acc[2 * ep], acc[2 * ep], bp0);
                ADD2(acc[2 * ep + 1], acc[2 * ep + 1], bp1);
            }
            uint32_t a0, a1, b0, b1v;
#pragma unroll
            for (int ep = 0; ep < 4; ep++) {
                int eA = ebase + 2 * ep;
                int dnA = sDst[eA], dnB = sDst[eA + 1];
                UNPK2(a0, b0, acc[2 * ep]);      // d0: (edge even, edge odd)
                UNPK2(a1, b1v, acc[2 * ep + 1]); // d1: (edge even, edge odd)
                if (dnA >= 0)
                    REDV2(&g_agg[(size_t)dnA * D + dd], __uint_as_float(a0), __uint_as_float(a1));
                if (dnB >= 0)
                    REDV2(&g_agg[(size_t)dnB * D + dd], __uint_as_float(b0), __uint_as_float(b1v));
            }
        }
        __syncthreads();
    }
}

// ---------------- pooling (relu fused) ----------------
__global__ void k_pool(const int* __restrict__ batch) {
    int i = blockIdx.x * blockDim.x + threadIdx.x;
    if (i >= NN * D) return;
    int n = i >> 6, d = i & 63;
    float v = fmaxf(g_h[i] + g_agg[i], 0.f);
    atomicAdd(&g_sums[batch[n] * D + d], v);
}

__global__ void k_count(const int* __restrict__ batch) {
    int n = blockIdx.x * blockDim.x + threadIdx.x;
    if (n >= NN) return;
    int b = batch[n];
    unsigned mask = __activemask();
    unsigned m = __match_any_sync(mask, b);
    int leader = __ffs(m) - 1;
    if ((threadIdx.x & 31) == leader) atomicAdd(&g_cnt[b], (float)__popc(m));
}

__global__ void k_final(const float* __restrict__ fcw, const float* __restrict__ fcb,
                        float* __restrict__ out) {
    int g = threadIdx.x;
    if (g < NG) {
        float c = fmaxf(g_cnt[g], 1.f);
        float s = 0.f;
#pragma unroll
        for (int d = 0; d < D; d++) s += g_sums[g * D + d] * fcw[d];
        out[g] = s / c + fcb[0];
    }
}

extern "C" void kernel_launch(void* const* d_in, const int* in_sizes, int n_in,
                              void* d_out, int out_size) {
    const int*   atoms = (const int*)d_in[0];
    const int*   ei    = (const int*)d_in[1];
    const float* coord = (const float*)d_in[2];
    const int*   isr   = (const int*)d_in[3];
    const int*   batch = (const int*)d_in[4];
    const float* embed = (const float*)d_in[5];
    const float* subw  = (const float*)d_in[6];
    const float* W1    = (const float*)d_in[7];
    const float* b1    = (const float*)d_in[8];
    const float* W2    = (const float*)d_in[9];
    const float* b2    = (const float*)d_in[10];
    const float* fcw   = (const float*)d_in[11];
    const float* fcb   = (const float*)d_in[12];
    float* out = (float*)d_out;

    cudaFuncSetAttribute(k_edge, cudaFuncAttributeMaxDynamicSharedMemorySize, SMEM_EDGE);

    const int T = 256;
    k_init_h<<<(NN * D + T - 1) / T, T>>>(atoms, embed);                       // 0
    k_edge_prep<<<(NE + 1024 + T - 1) / T, T>>>(ei, coord, isr, subw, W1, b1); // 1

    for (int l = 0; l < NL; l++) {
        k_nodegemm<<<NN / 16, 256>>>(W1, l);                                   // 2,4,6,8
        k_edge<<<EGRID, ETHREADS, SMEM_EDGE>>>(W1, W2, b2, ei, l);             // 3,5,7,9
    }

    k_pool<<<(NN * D + T - 1) / T, T>>>(batch);
    k_count<<<(NN + T - 1) / T, T>>>(batch);
    k_final<<<1, 64>>>(fcw, fcb, out);
}